// round 14
// baseline (speedup 1.0000x reference)
#include <cuda_runtime.h>
#include <cuda_bf16.h>
#include <math.h>

// Problem constants (fixed shapes)
#define NN      4096      // nodes
#define KIN     1433      // in features
#define NH      8         // heads
#define FOUT    64        // NH*DHD
#define LRELU   0.2f

// Attention tiling
#define TIA     64        // i rows per block
#define TJ      64        // j tile
#define SPLITS  16        // j-axis splits (1024 blocks -> best wave utilization at 3 blocks/SM)
#define CHUNK   (NN / SPLITS)   // 256
#define NTILES  (CHUNK / TJ)    // 4 tiles per block

// GEMM split-K (128x64 tiles, 256 threads, 4x8 per thread)
#define GM      128
#define KSPL    8
#define KCH     180       // ceil(1433/8)

// fused launch role split (all blocks 256 threads)
#define GEMM_BLOCKS  (32 * KSPL)                 // 256
#define PACK_BLOCKS  ((NN * NN / 16) / 256)      // 4096 (16 ints per thread)

typedef unsigned long long u64;

// ---------------- scratch (no allocations allowed) ----------------
__device__ __align__(16) float2 Lbuf[NN * NH];               // (e^sl, e^{0.2 sl})
__device__ __align__(16) float2 Rbuf[NN * NH];               // (e^sr, e^{0.2 sr})
__device__ __align__(16) u64 gt_buf[(NN / 64) * 2048];       // 1 MB: tf32 G pairs [tile][j8][hd][j4]
__device__ __align__(16) unsigned int emask_buf[NN * (NN / 32)]; // 2 MB: edge bitmask
__device__ __align__(16) float pacc_buf[SPLITS * NN * FOUT]; // 16 MB (gemm uses 8 slices; attn 16)
__device__ __align__(16) float psum_buf[SPLITS * NN * NH];   // 2 MB partial denom

// f32x2 packed helpers (Blackwell; PTX-only). "l" constraint = 64-bit int reg.
__device__ __forceinline__ u64 ffma2(u64 a, u64 b, u64 c) {
    u64 d;
    asm("fma.rn.f32x2 %0, %1, %2, %3;" : "=l"(d) : "l"(a), "l"(b), "l"(c));
    return d;
}
__device__ __forceinline__ u64 fmul2(u64 a, u64 b) {
    u64 d;
    asm("mul.rn.f32x2 %0, %1, %2;" : "=l"(d) : "l"(a), "l"(b));
    return d;
}
__device__ __forceinline__ u64 pack2(float lo, float hi) {
    u64 d;
    asm("mov.b64 %0, {%1, %2};" : "=l"(d) : "f"(lo), "f"(hi));
    return d;
}
__device__ __forceinline__ void unpack2(u64 d, float& lo, float& hi) {
    asm("mov.b64 {%0, %1}, %2;" : "=f"(lo), "=f"(hi) : "l"(d));
}
__device__ __forceinline__ unsigned int tf32_rna(float f) {
    unsigned int r;
    asm("cvt.rna.tf32.f32 %0, %1;" : "=r"(r) : "f"(f));
    return r;
}
// w = tf32-truncate((max of both lrelu branches) masked by mu) — one 3-input LOP3.
__device__ __forceinline__ float wmax(u64 eifi, u64 ef, unsigned int mu) {
    const u64 p = fmul2(eifi, ef);
    float lo, hi; unpack2(p, lo, hi);
    const float mx = fmaxf(lo, hi);                                     // FMNMX (alu)
    return __uint_as_float(__float_as_uint(mx) & mu & 0xFFFFE000u);     // LOP3 (alu)
}
// tf32 mma: D += A(16x8) * B(8x8), A values already on tf32 grid
__device__ __forceinline__ void mma_tf32(float* d, float a0, float a1, float a2, float a3,
                                         unsigned int b0, unsigned int b1) {
    asm volatile(
        "mma.sync.aligned.m16n8k8.row.col.f32.tf32.tf32.f32 "
        "{%0,%1,%2,%3}, {%4,%5,%6,%7}, {%8,%9}, {%0,%1,%2,%3};"
        : "+f"(d[0]), "+f"(d[1]), "+f"(d[2]), "+f"(d[3])
        : "r"(__float_as_uint(a0)), "r"(__float_as_uint(a1)),
          "r"(__float_as_uint(a2)), "r"(__float_as_uint(a3)),
          "r"(b0), "r"(b1));
}
// cp.async helpers
__device__ __forceinline__ unsigned int smem_u32(const void* p) {
    return (unsigned int)__cvta_generic_to_shared(p);
}
__device__ __forceinline__ void cp16(unsigned int saddr, const void* g) {
    asm volatile("cp.async.cg.shared.global [%0], [%1], 16;" :: "r"(saddr), "l"(g) : "memory");
}
__device__ __forceinline__ void cp_commit() {
    asm volatile("cp.async.commit_group;" ::: "memory");
}
template <int N>
__device__ __forceinline__ void cp_wait() {
    asm volatile("cp.async.wait_group %0;" :: "n"(N) : "memory");
}

// ---------------- Kernel 1: FUSED  g-projection GEMM  +  edge bit-packing ----------------
__global__ void __launch_bounds__(256) fused_gemm_pack(const float* __restrict__ A,
                                                       const float* __restrict__ B,
                                                       const int* __restrict__ edge)
{
    if (blockIdx.x >= GEMM_BLOCKS) {
        // ---- edge pack role: 16 ints -> 16 bits per thread ----
        const int t    = (blockIdx.x - GEMM_BLOCKS) * 256 + threadIdx.x;
        const int lane = threadIdx.x & 31;
        const int4* e4 = (const int4*)edge;
        unsigned int b16 = 0;
        #pragma unroll
        for (int q = 0; q < 4; q++) {
            const int4 v = e4[(size_t)t * 4 + q];
            b16 |= (v.x != 0 ? 1u : 0u) << (q * 4 + 0);
            b16 |= (v.y != 0 ? 1u : 0u) << (q * 4 + 1);
            b16 |= (v.z != 0 ? 1u : 0u) << (q * 4 + 2);
            b16 |= (v.w != 0 ? 1u : 0u) << (q * 4 + 3);
        }
        unsigned int val = b16 << (16 * (lane & 1));
        val |= __shfl_xor_sync(0xFFFFFFFFu, val, 1);
        if ((lane & 1) == 0) emask_buf[t >> 1] = val;
        return;
    }

    // ---- gemm role: 128x64 tile, 256 threads, 4 rows x 8 cols each ----
    __shared__ u64   Asd[16][132];  // (a,a) dup pairs; even stride -> 16B-aligned rows
    __shared__ float Bs[16][68];
    const int tid = threadIdx.x;
    const int mb  = blockIdx.x & 31;
    const int spl = blockIdx.x >> 5;
    const int m0  = mb * GM;
    const int kb  = spl * KCH;
    const int ke  = min(KIN, kb + KCH);
    const int tx  = tid & 7;       // cols tx*8..+7
    const int ty  = tid >> 3;      // rows ty*4..+3 (ty 0..31)

    u64 acc[4][4] = {};

    for (int k0 = kb; k0 < ke; k0 += 16) {
        {
            const int kk  = tid & 15;
            const int rb  = tid >> 4;          // 0..15
            const bool ok = (k0 + kk < ke);
            #pragma unroll
            for (int p = 0; p < 8; p++) {
                const int row = rb + p * 16;
                const float v = ok ? A[(size_t)(m0 + row) * KIN + k0 + kk] : 0.f;
                Asd[kk][row] = pack2(v, v);
            }
        }
        {
            const int rr = tid >> 4;
            const int c4 = tid & 15;
            float4 v = make_float4(0.f, 0.f, 0.f, 0.f);
            if (k0 + rr < ke) v = *(const float4*)&B[(size_t)(k0 + rr) * 64 + c4 * 4];
            *(float4*)&Bs[rr][c4 * 4] = v;
        }
        __syncthreads();

        #pragma unroll
        for (int kk = 0; kk < 16; kk++) {
            const ulonglong2 a01 = *(const ulonglong2*)&Asd[kk][ty * 4 + 0];
            const ulonglong2 a23 = *(const ulonglong2*)&Asd[kk][ty * 4 + 2];
            const ulonglong2 b01 = *(const ulonglong2*)&Bs[kk][tx * 8 + 0];
            const ulonglong2 b23 = *(const ulonglong2*)&Bs[kk][tx * 8 + 4];
            const u64 ar[4] = {a01.x, a01.y, a23.x, a23.y};
            #pragma unroll
            for (int r = 0; r < 4; r++) {
                acc[r][0] = ffma2(ar[r], b01.x, acc[r][0]);
                acc[r][1] = ffma2(ar[r], b01.y, acc[r][1]);
                acc[r][2] = ffma2(ar[r], b23.x, acc[r][2]);
                acc[r][3] = ffma2(ar[r], b23.y, acc[r][3]);
            }
        }
        __syncthreads();
    }

    #pragma unroll
    for (int r = 0; r < 4; r++) {
        float x0, x1, x2, x3, x4, x5, x6, x7;
        unpack2(acc[r][0], x0, x1);
        unpack2(acc[r][1], x2, x3);
        unpack2(acc[r][2], x4, x5);
        unpack2(acc[r][3], x6, x7);
        float* p = &pacc_buf[((size_t)spl * NN + m0 + ty * 4 + r) * 64 + tx * 8];
        *(float4*)(p + 0) = make_float4(x0, x1, x2, x3);
        *(float4*)(p + 4) = make_float4(x4, x5, x6, x7);
    }
}

// ---------------- Kernel 2: reduce split-K + factored exps + pack tf32 G tiles ----------------
__global__ void __launch_bounds__(256) prep_scores(const float* __restrict__ a_l,
                                                   const float* __restrict__ a_r)
{
    const int t = blockIdx.x * blockDim.x + threadIdx.x;
    const int n = t >> 3;
    const int h = t & 7;

    float4 s0 = make_float4(0.f, 0.f, 0.f, 0.f);
    float4 s1 = s0;
    #pragma unroll
    for (int s = 0; s < KSPL; s++) {
        const float* p = &pacc_buf[((size_t)s * NN + n) * 64 + h * 8];
        const float4 p0 = *(const float4*)(p + 0);
        const float4 p1 = *(const float4*)(p + 4);
        s0.x += p0.x; s0.y += p0.y; s0.z += p0.z; s0.w += p0.w;
        s1.x += p1.x; s1.y += p1.y; s1.z += p1.z; s1.w += p1.w;
    }

    // pack tf32 G into attn tile layout: word idx = (((tile*8+j8)*64+hd)*4 + j4)*2 + half
    {
        const int tile = n >> 6;
        const int j8v  = (n >> 3) & 7;
        const int j4v  = n & 3;
        const int half = (n >> 2) & 1;
        unsigned int* gt32 = (unsigned int*)gt_buf;
        const float gv[8] = {s0.x, s0.y, s0.z, s0.w, s1.x, s1.y, s1.z, s1.w};
        #pragma unroll
        for (int d = 0; d < 8; d++) {
            const int hd = h * 8 + d;
            const size_t widx = ((((size_t)tile * 8 + j8v) * 64 + hd) * 4 + j4v) * 2 + half;
            gt32[widx] = tf32_rna(gv[d]);
        }
    }

    const float4 al0 = *(const float4*)&a_l[h * 8 + 0];
    const float4 al1 = *(const float4*)&a_l[h * 8 + 4];
    const float4 ar0 = *(const float4*)&a_r[h * 8 + 0];
    const float4 ar1 = *(const float4*)&a_r[h * 8 + 4];

    const float sl = s0.x*al0.x + s0.y*al0.y + s0.z*al0.z + s0.w*al0.w
                   + s1.x*al1.x + s1.y*al1.y + s1.z*al1.z + s1.w*al1.w;
    const float sr = s0.x*ar0.x + s0.y*ar0.y + s0.z*ar0.z + s0.w*ar0.w
                   + s1.x*ar1.x + s1.y*ar1.y + s1.z*ar1.z + s1.w*ar1.w;

    Lbuf[t] = make_float2(expf(sl), expf(LRELU * sl));
    Rbuf[t] = make_float2(expf(sr), expf(LRELU * sr));
}

// ---------------- Kernel 3: masked softmax-aggregation, cp.async double-buffered ----------------
__global__ void __launch_bounds__(256, 3) attn_kernel()
{
    __shared__ u64 gp[2][8][64][4];   // 32 KB ping-pong: tf32 G pairs
    __shared__ u64 rsu[2][512];       // 8 KB ping-pong: (e^sr, e^{.2 sr}) per (j,h)

    const int tid  = threadIdx.x;
    const int lane = tid & 31;
    const int wrp  = tid >> 5;
    const int gid  = lane >> 2;
    const int tig  = lane & 3;
    const int rw   = (wrp & 3) * 16;
    const int hb   = (wrp >> 2) * 4;
    const int split = blockIdx.x;
    const int i0   = blockIdx.y * TIA;

    const u64* Lu = (const u64*)Lbuf;
    const u64* Ru = (const u64*)Rbuf;
    const u64* em = (const u64*)emask_buf;   // [NN][64] u64 mask rows

    u64 EiF[4][2];
    #pragma unroll
    for (int hh = 0; hh < 4; hh++) {
        EiF[hh][0] = Lu[(size_t)(i0 + rw + gid) * 8 + hb + hh];
        EiF[hh][1] = Lu[(size_t)(i0 + rw + gid + 8) * 8 + hb + hh];
    }
    const int r0 = i0 + rw + gid;
    const int r1 = r0 + 8;

    float accG[4][4] = {};
    float sL0[4] = {}, sL1[4] = {};

    const int tile0 = split * NTILES;    // global 64-j tile index base

    #define STAGE(bufi, gtile)                                                        \
    {                                                                                 \
        const u64* gsrc = gt_buf + (size_t)(gtile) * 2048;                            \
        const unsigned int gdst = smem_u32(&gp[bufi][0][0][0]);                       \
        _Pragma("unroll")                                                             \
        for (int k = 0; k < 4; k++)                                                   \
            cp16(gdst + (unsigned)(tid + k * 256) * 16, gsrc + (tid + k * 256) * 2);  \
        const u64* rsrc = Ru + (size_t)(gtile) * 64 * 8;                              \
        cp16(smem_u32(&rsu[bufi][0]) + (unsigned)tid * 16, rsrc + tid * 2);           \
    }

    STAGE(0, tile0);
    cp_commit();

    for (int t = 0; t < NTILES; t++) {
        if (t + 1 < NTILES) { STAGE((t + 1) & 1, tile0 + t + 1); cp_commit(); }
        if (t + 1 < NTILES) cp_wait<1>(); else cp_wait<0>();
        __syncthreads();

        const int gtile = tile0 + t;
        const u64 m0 = em[(size_t)r0 * 64 + gtile];
        const u64 m1 = em[(size_t)r1 * 64 + gtile];
        const int buf = t & 1;

        #pragma unroll 2
        for (int j8 = 0; j8 < 8; j8++) {
            const unsigned int b0 = (unsigned int)(m0 >> (j8 * 8));
            const unsigned int b1 = (unsigned int)(m1 >> (j8 * 8));
            const unsigned int mu0 = (unsigned int)(-(int)((b0 >> tig) & 1u));
            const unsigned int mu1 = (unsigned int)(-(int)((b1 >> tig) & 1u));
            const unsigned int mu2 = (unsigned int)(-(int)((b0 >> (tig + 4)) & 1u));
            const unsigned int mu3 = (unsigned int)(-(int)((b1 >> (tig + 4)) & 1u));

            const ulonglong2 e0a = *(const ulonglong2*)&rsu[buf][(j8 * 8 + tig) * 8 + hb];
            const ulonglong2 e0b = *(const ulonglong2*)&rsu[buf][(j8 * 8 + tig) * 8 + hb + 2];
            const ulonglong2 e1a = *(const ulonglong2*)&rsu[buf][(j8 * 8 + tig + 4) * 8 + hb];
            const ulonglong2 e1b = *(const ulonglong2*)&rsu[buf][(j8 * 8 + tig + 4) * 8 + hb + 2];
            const u64 EF0[4] = {e0a.x, e0a.y, e0b.x, e0b.y};
            const u64 EF1[4] = {e1a.x, e1a.y, e1b.x, e1b.y};
            #pragma unroll
            for (int hh = 0; hh < 4; hh++) {
                const int h = hb + hh;
                const float a0 = wmax(EiF[hh][0], EF0[hh], mu0);
                const float a1 = wmax(EiF[hh][1], EF0[hh], mu1);
                const float a2 = wmax(EiF[hh][0], EF1[hh], mu2);
                const float a3 = wmax(EiF[hh][1], EF1[hh], mu3);
                sL0[hh] += a0 + a2;
                sL1[hh] += a1 + a3;
                const uint2 b = *(const uint2*)&gp[buf][j8][h * 8 + gid][tig];
                mma_tf32(accG[hh], a0, a1, a2, a3, b.x, b.y);
            }
        }
        __syncthreads();   // all warps done with buf before it is restaged
    }

    // epilogue: reduce denominators over the 4-lane tig group, write partials
    #pragma unroll
    for (int hh = 0; hh < 4; hh++) {
        float s0 = sL0[hh], s1 = sL1[hh];
        s0 += __shfl_xor_sync(0xFFFFFFFFu, s0, 1);
        s0 += __shfl_xor_sync(0xFFFFFFFFu, s0, 2);
        s1 += __shfl_xor_sync(0xFFFFFFFFu, s1, 1);
        s1 += __shfl_xor_sync(0xFFFFFFFFu, s1, 2);

        const int h = hb + hh;
        float* p0 = &pacc_buf[((size_t)split * NN + r0) * 64 + h * 8 + tig * 2];
        float* p1 = &pacc_buf[((size_t)split * NN + r1) * 64 + h * 8 + tig * 2];
        *(float2*)p0 = make_float2(accG[hh][0], accG[hh][1]);
        *(float2*)p1 = make_float2(accG[hh][2], accG[hh][3]);
        if (tig == 0) {
            psum_buf[((size_t)split * NN + r0) * 8 + h] = s0;
            psum_buf[((size_t)split * NN + r1) * 8 + h] = s1;
        }
    }
}

// ---------------- Kernel 4: combine splits, normalize, ELU ----------------
__global__ void __launch_bounds__(256) combine_kernel(float* __restrict__ out)
{
    const int t = blockIdx.x * blockDim.x + threadIdx.x;   // 0 .. NN*64-1
    const int i = t >> 6;
    const int c = t & 63;
    const int h = c >> 3;

    float a = 0.f, den = 0.f;
    #pragma unroll
    for (int s = 0; s < SPLITS; s++) {
        a   += pacc_buf[((size_t)s * NN + i) * 64 + c];
        den += psum_buf[((size_t)s * NN + i) * 8 + h];
    }
    const float v = a / den;
    out[t] = (v >= 0.f) ? v : expm1f(v);
}

// ---------------- launch ----------------
extern "C" void kernel_launch(void* const* d_in, const int* in_sizes, int n_in,
                              void* d_out, int out_size)
{
    const float* vert = (const float*)d_in[0];   // [4096,1433]
    const int*   edge = (const int*)  d_in[1];   // [4096,4096]
    const float* W    = (const float*)d_in[2];   // [1433,64]
    const float* a_l  = (const float*)d_in[3];   // [8,8]
    const float* a_r  = (const float*)d_in[4];   // [8,8]
    float* out = (float*)d_out;                  // [4096,64]

    fused_gemm_pack<<<GEMM_BLOCKS + PACK_BLOCKS, 256>>>(vert, W, edge);
    prep_scores<<<(NN * NH) / 256, 256>>>(a_l, a_r);
    attn_kernel<<<dim3(SPLITS, NN / TIA), 256>>>();
    combine_kernel<<<(NN * FOUT) / 256, 256>>>(out);
}

// round 15
// speedup vs baseline: 1.0921x; 1.0921x over previous
#include <cuda_runtime.h>
#include <cuda_bf16.h>
#include <math.h>

// Problem constants (fixed shapes)
#define NN      4096      // nodes
#define KIN     1433      // in features
#define NH      8         // heads
#define FOUT    64        // NH*DHD
#define LRELU   0.2f

// Attention tiling
#define TIA     64        // i rows per block
#define TJ      64        // j tile
#define SPLITS  8         // j-axis splits
#define CHUNK   (NN / SPLITS)   // 512
#define NTILES  (CHUNK / TJ)    // 8 tiles per block

// GEMM split-K (128x64 tiles, 256 threads, 4x8 per thread)
#define GM      128
#define KSPL    16
#define KCH     90        // ceil(1433/16)

// fused launch role split (all blocks 256 threads)
#define GEMM_BLOCKS  (32 * KSPL)                 // 512
#define PACK_BLOCKS  ((NN * NN / 16) / 256)      // 4096 (16 ints per thread)

typedef unsigned long long u64;

// ---------------- scratch (no allocations allowed) ----------------
__device__ __align__(16) float2 Lbuf[NN * NH];               // (e^sl, e^{0.2 sl})
__device__ __align__(16) float2 Rbuf[NN * NH];               // (e^sr, e^{0.2 sr})
__device__ __align__(16) u64 gt_buf[(NN / 64) * 2048];       // 1 MB: tf32 G pairs [tile][j8][hd][j4]
__device__ __align__(16) unsigned int emask_buf[NN * (NN / 32)]; // 2 MB: edge bitmask
__device__ __align__(16) float pacc_buf[KSPL * NN * FOUT];   // 16 MB (gemm partials; attn reuses 8 slices)
__device__ __align__(16) float psum_buf[SPLITS * NN * NH];   // 1 MB partial denom

// f32x2 packed helpers (Blackwell; PTX-only). "l" constraint = 64-bit int reg.
__device__ __forceinline__ u64 ffma2(u64 a, u64 b, u64 c) {
    u64 d;
    asm("fma.rn.f32x2 %0, %1, %2, %3;" : "=l"(d) : "l"(a), "l"(b), "l"(c));
    return d;
}
__device__ __forceinline__ u64 fmul2(u64 a, u64 b) {
    u64 d;
    asm("mul.rn.f32x2 %0, %1, %2;" : "=l"(d) : "l"(a), "l"(b));
    return d;
}
__device__ __forceinline__ u64 pack2(float lo, float hi) {
    u64 d;
    asm("mov.b64 %0, {%1, %2};" : "=l"(d) : "f"(lo), "f"(hi));
    return d;
}
__device__ __forceinline__ void unpack2(u64 d, float& lo, float& hi) {
    asm("mov.b64 {%0, %1}, %2;" : "=f"(lo), "=f"(hi) : "l"(d));
}
__device__ __forceinline__ unsigned int tf32_rna(float f) {
    unsigned int r;
    asm("cvt.rna.tf32.f32 %0, %1;" : "=r"(r) : "f"(f));
    return r;
}
// w = tf32-truncate((max of both lrelu branches) masked by mu) — one 3-input LOP3.
__device__ __forceinline__ float wmax(u64 eifi, u64 ef, unsigned int mu) {
    const u64 p = fmul2(eifi, ef);
    float lo, hi; unpack2(p, lo, hi);
    const float mx = fmaxf(lo, hi);                                     // FMNMX (alu)
    return __uint_as_float(__float_as_uint(mx) & mu & 0xFFFFE000u);     // LOP3 (alu)
}
// tf32 mma: D += A(16x8) * B(8x8), A values already on tf32 grid
__device__ __forceinline__ void mma_tf32(float* d, float a0, float a1, float a2, float a3,
                                         unsigned int b0, unsigned int b1) {
    asm volatile(
        "mma.sync.aligned.m16n8k8.row.col.f32.tf32.tf32.f32 "
        "{%0,%1,%2,%3}, {%4,%5,%6,%7}, {%8,%9}, {%0,%1,%2,%3};"
        : "+f"(d[0]), "+f"(d[1]), "+f"(d[2]), "+f"(d[3])
        : "r"(__float_as_uint(a0)), "r"(__float_as_uint(a1)),
          "r"(__float_as_uint(a2)), "r"(__float_as_uint(a3)),
          "r"(b0), "r"(b1));
}
// cp.async helpers
__device__ __forceinline__ unsigned int smem_u32(const void* p) {
    return (unsigned int)__cvta_generic_to_shared(p);
}
__device__ __forceinline__ void cp16(unsigned int saddr, const void* g) {
    asm volatile("cp.async.cg.shared.global [%0], [%1], 16;" :: "r"(saddr), "l"(g) : "memory");
}
__device__ __forceinline__ void cp_commit() {
    asm volatile("cp.async.commit_group;" ::: "memory");
}
template <int N>
__device__ __forceinline__ void cp_wait() {
    asm volatile("cp.async.wait_group %0;" :: "n"(N) : "memory");
}

// ---------------- Kernel 1: FUSED  g-projection GEMM  +  edge bit-packing ----------------
__global__ void __launch_bounds__(256) fused_gemm_pack(const float* __restrict__ A,
                                                       const float* __restrict__ B,
                                                       const int* __restrict__ edge)
{
    if (blockIdx.x >= GEMM_BLOCKS) {
        // ---- edge pack role: 16 ints -> 16 bits per thread ----
        const int t    = (blockIdx.x - GEMM_BLOCKS) * 256 + threadIdx.x;
        const int lane = threadIdx.x & 31;
        const int4* e4 = (const int4*)edge;
        unsigned int b16 = 0;
        #pragma unroll
        for (int q = 0; q < 4; q++) {
            const int4 v = e4[(size_t)t * 4 + q];
            b16 |= (v.x != 0 ? 1u : 0u) << (q * 4 + 0);
            b16 |= (v.y != 0 ? 1u : 0u) << (q * 4 + 1);
            b16 |= (v.z != 0 ? 1u : 0u) << (q * 4 + 2);
            b16 |= (v.w != 0 ? 1u : 0u) << (q * 4 + 3);
        }
        unsigned int val = b16 << (16 * (lane & 1));
        val |= __shfl_xor_sync(0xFFFFFFFFu, val, 1);
        if ((lane & 1) == 0) emask_buf[t >> 1] = val;
        return;
    }

    // ---- gemm role: 128x64 tile, 256 threads, 4 rows x 8 cols each ----
    __shared__ u64   Asd[16][132];  // (a,a) dup pairs; even stride -> 16B-aligned rows
    __shared__ float Bs[16][68];
    const int tid = threadIdx.x;
    const int mb  = blockIdx.x & 31;
    const int spl = blockIdx.x >> 5;
    const int m0  = mb * GM;
    const int kb  = spl * KCH;
    const int ke  = min(KIN, kb + KCH);
    const int tx  = tid & 7;       // cols tx*8..+7
    const int ty  = tid >> 3;      // rows ty*4..+3 (ty 0..31)

    u64 acc[4][4] = {};

    for (int k0 = kb; k0 < ke; k0 += 16) {
        {
            const int kk  = tid & 15;
            const int rb  = tid >> 4;          // 0..15
            const bool ok = (k0 + kk < ke);
            #pragma unroll
            for (int p = 0; p < 8; p++) {
                const int row = rb + p * 16;
                const float v = ok ? A[(size_t)(m0 + row) * KIN + k0 + kk] : 0.f;
                Asd[kk][row] = pack2(v, v);
            }
        }
        {
            const int rr = tid >> 4;
            const int c4 = tid & 15;
            float4 v = make_float4(0.f, 0.f, 0.f, 0.f);
            if (k0 + rr < ke) v = *(const float4*)&B[(size_t)(k0 + rr) * 64 + c4 * 4];
            *(float4*)&Bs[rr][c4 * 4] = v;
        }
        __syncthreads();

        #pragma unroll
        for (int kk = 0; kk < 16; kk++) {
            const ulonglong2 a01 = *(const ulonglong2*)&Asd[kk][ty * 4 + 0];
            const ulonglong2 a23 = *(const ulonglong2*)&Asd[kk][ty * 4 + 2];
            const ulonglong2 b01 = *(const ulonglong2*)&Bs[kk][tx * 8 + 0];
            const ulonglong2 b23 = *(const ulonglong2*)&Bs[kk][tx * 8 + 4];
            const u64 ar[4] = {a01.x, a01.y, a23.x, a23.y};
            #pragma unroll
            for (int r = 0; r < 4; r++) {
                acc[r][0] = ffma2(ar[r], b01.x, acc[r][0]);
                acc[r][1] = ffma2(ar[r], b01.y, acc[r][1]);
                acc[r][2] = ffma2(ar[r], b23.x, acc[r][2]);
                acc[r][3] = ffma2(ar[r], b23.y, acc[r][3]);
            }
        }
        __syncthreads();
    }

    #pragma unroll
    for (int r = 0; r < 4; r++) {
        float x0, x1, x2, x3, x4, x5, x6, x7;
        unpack2(acc[r][0], x0, x1);
        unpack2(acc[r][1], x2, x3);
        unpack2(acc[r][2], x4, x5);
        unpack2(acc[r][3], x6, x7);
        float* p = &pacc_buf[((size_t)spl * NN + m0 + ty * 4 + r) * 64 + tx * 8];
        *(float4*)(p + 0) = make_float4(x0, x1, x2, x3);
        *(float4*)(p + 4) = make_float4(x4, x5, x6, x7);
    }
}

// ---------------- Kernel 2: reduce split-K + factored exps + pack tf32 G tiles ----------------
// 4 threads per (n,h), one per dim-pair: 512 blocks, coalesced 8B loads, shfl dot-reduce.
__global__ void __launch_bounds__(256) prep_scores(const float* __restrict__ a_l,
                                                   const float* __restrict__ a_r)
{
    const int t  = blockIdx.x * blockDim.x + threadIdx.x;   // NN*NH*4 threads
    const int n  = t >> 5;
    const int h  = (t >> 2) & 7;
    const int dp = t & 3;        // dim pair: dims 2dp, 2dp+1

    float2 s = make_float2(0.f, 0.f);
    #pragma unroll
    for (int sp = 0; sp < KSPL; sp++) {
        const float2 p = *(const float2*)&pacc_buf[((size_t)sp * NN + n) * 64 + h * 8 + dp * 2];
        s.x += p.x; s.y += p.y;
    }

    // pack tf32 G into attn tile layout: word idx = (((tile*8+j8)*64+hd)*4 + j4)*2 + half
    {
        const int tile = n >> 6;
        const int j8v  = (n >> 3) & 7;
        const int j4v  = n & 3;
        const int half = (n >> 2) & 1;
        unsigned int* gt32 = (unsigned int*)gt_buf;
        const int hd0 = h * 8 + dp * 2;
        const size_t base = ((size_t)tile * 8 + j8v) * 64;
        gt32[((base + hd0 + 0) * 4 + j4v) * 2 + half] = tf32_rna(s.x);
        gt32[((base + hd0 + 1) * 4 + j4v) * 2 + half] = tf32_rna(s.y);
    }

    // partial attention dots, reduce over the 4-lane dp group
    const float al0 = a_l[h * 8 + dp * 2], al1 = a_l[h * 8 + dp * 2 + 1];
    const float ar0 = a_r[h * 8 + dp * 2], ar1 = a_r[h * 8 + dp * 2 + 1];
    float sl = s.x * al0 + s.y * al1;
    float sr = s.x * ar0 + s.y * ar1;
    sl += __shfl_xor_sync(0xFFFFFFFFu, sl, 1);
    sl += __shfl_xor_sync(0xFFFFFFFFu, sl, 2);
    sr += __shfl_xor_sync(0xFFFFFFFFu, sr, 1);
    sr += __shfl_xor_sync(0xFFFFFFFFu, sr, 2);

    if (dp == 0) {
        Lbuf[n * 8 + h] = make_float2(expf(sl), expf(LRELU * sl));
        Rbuf[n * 8 + h] = make_float2(expf(sr), expf(LRELU * sr));
    }
}

// ---------------- Kernel 3: masked softmax-aggregation, cp.async double-buffered ----------------
__global__ void __launch_bounds__(256, 3) attn_kernel()
{
    __shared__ u64 gp[2][8][64][4];   // 32 KB ping-pong: tf32 G pairs
    __shared__ u64 rsu[2][512];       // 8 KB ping-pong: (e^sr, e^{.2 sr}) per (j,h)

    const int tid  = threadIdx.x;
    const int lane = tid & 31;
    const int wrp  = tid >> 5;
    const int gid  = lane >> 2;
    const int tig  = lane & 3;
    const int rw   = (wrp & 3) * 16;
    const int hb   = (wrp >> 2) * 4;
    const int split = blockIdx.x;
    const int i0   = blockIdx.y * TIA;

    const u64* Lu = (const u64*)Lbuf;
    const u64* Ru = (const u64*)Rbuf;
    const u64* em = (const u64*)emask_buf;   // [NN][64] u64 mask rows

    u64 EiF[4][2];
    #pragma unroll
    for (int hh = 0; hh < 4; hh++) {
        EiF[hh][0] = Lu[(size_t)(i0 + rw + gid) * 8 + hb + hh];
        EiF[hh][1] = Lu[(size_t)(i0 + rw + gid + 8) * 8 + hb + hh];
    }
    const int r0 = i0 + rw + gid;
    const int r1 = r0 + 8;

    float accG[4][4] = {};
    float sL0[4] = {}, sL1[4] = {};

    const int tile0 = split * NTILES;    // global 64-j tile index base

    #define STAGE(bufi, gtile)                                                        \
    {                                                                                 \
        const u64* gsrc = gt_buf + (size_t)(gtile) * 2048;                            \
        const unsigned int gdst = smem_u32(&gp[bufi][0][0][0]);                       \
        _Pragma("unroll")                                                             \
        for (int k = 0; k < 4; k++)                                                   \
            cp16(gdst + (unsigned)(tid + k * 256) * 16, gsrc + (tid + k * 256) * 2);  \
        const u64* rsrc = Ru + (size_t)(gtile) * 64 * 8;                              \
        cp16(smem_u32(&rsu[bufi][0]) + (unsigned)tid * 16, rsrc + tid * 2);           \
    }

    STAGE(0, tile0);
    cp_commit();

    for (int t = 0; t < NTILES; t++) {
        if (t + 1 < NTILES) { STAGE((t + 1) & 1, tile0 + t + 1); cp_commit(); }
        if (t + 1 < NTILES) cp_wait<1>(); else cp_wait<0>();
        __syncthreads();

        const int gtile = tile0 + t;
        const u64 m0 = em[(size_t)r0 * 64 + gtile];
        const u64 m1 = em[(size_t)r1 * 64 + gtile];
        const int buf = t & 1;

        #pragma unroll 2
        for (int j8 = 0; j8 < 8; j8++) {
            const unsigned int b0 = (unsigned int)(m0 >> (j8 * 8));
            const unsigned int b1 = (unsigned int)(m1 >> (j8 * 8));
            const unsigned int mu0 = (unsigned int)(-(int)((b0 >> tig) & 1u));
            const unsigned int mu1 = (unsigned int)(-(int)((b1 >> tig) & 1u));
            const unsigned int mu2 = (unsigned int)(-(int)((b0 >> (tig + 4)) & 1u));
            const unsigned int mu3 = (unsigned int)(-(int)((b1 >> (tig + 4)) & 1u));

            const ulonglong2 e0a = *(const ulonglong2*)&rsu[buf][(j8 * 8 + tig) * 8 + hb];
            const ulonglong2 e0b = *(const ulonglong2*)&rsu[buf][(j8 * 8 + tig) * 8 + hb + 2];
            const ulonglong2 e1a = *(const ulonglong2*)&rsu[buf][(j8 * 8 + tig + 4) * 8 + hb];
            const ulonglong2 e1b = *(const ulonglong2*)&rsu[buf][(j8 * 8 + tig + 4) * 8 + hb + 2];
            const u64 EF0[4] = {e0a.x, e0a.y, e0b.x, e0b.y};
            const u64 EF1[4] = {e1a.x, e1a.y, e1b.x, e1b.y};
            #pragma unroll
            for (int hh = 0; hh < 4; hh++) {
                const int h = hb + hh;
                const float a0 = wmax(EiF[hh][0], EF0[hh], mu0);
                const float a1 = wmax(EiF[hh][1], EF0[hh], mu1);
                const float a2 = wmax(EiF[hh][0], EF1[hh], mu2);
                const float a3 = wmax(EiF[hh][1], EF1[hh], mu3);
                sL0[hh] += a0 + a2;
                sL1[hh] += a1 + a3;
                const uint2 b = *(const uint2*)&gp[buf][j8][h * 8 + gid][tig];
                mma_tf32(accG[hh], a0, a1, a2, a3, b.x, b.y);
            }
        }
        __syncthreads();   // all warps done with buf before it is restaged
    }

    // epilogue: reduce denominators over the 4-lane tig group, write partials
    #pragma unroll
    for (int hh = 0; hh < 4; hh++) {
        float s0 = sL0[hh], s1 = sL1[hh];
        s0 += __shfl_xor_sync(0xFFFFFFFFu, s0, 1);
        s0 += __shfl_xor_sync(0xFFFFFFFFu, s0, 2);
        s1 += __shfl_xor_sync(0xFFFFFFFFu, s1, 1);
        s1 += __shfl_xor_sync(0xFFFFFFFFu, s1, 2);

        const int h = hb + hh;
        float* p0 = &pacc_buf[((size_t)split * NN + r0) * 64 + h * 8 + tig * 2];
        float* p1 = &pacc_buf[((size_t)split * NN + r1) * 64 + h * 8 + tig * 2];
        *(float2*)p0 = make_float2(accG[hh][0], accG[hh][1]);
        *(float2*)p1 = make_float2(accG[hh][2], accG[hh][3]);
        if (tig == 0) {
            psum_buf[((size_t)split * NN + r0) * 8 + h] = s0;
            psum_buf[((size_t)split * NN + r1) * 8 + h] = s1;
        }
    }
}

// ---------------- Kernel 4: combine splits, normalize, ELU ----------------
__global__ void __launch_bounds__(256) combine_kernel(float* __restrict__ out)
{
    const int t = blockIdx.x * blockDim.x + threadIdx.x;   // 0 .. NN*64-1
    const int i = t >> 6;
    const int c = t & 63;
    const int h = c >> 3;

    float a = 0.f, den = 0.f;
    #pragma unroll
    for (int s = 0; s < SPLITS; s++) {
        a   += pacc_buf[((size_t)s * NN + i) * 64 + c];
        den += psum_buf[((size_t)s * NN + i) * 8 + h];
    }
    const float v = a / den;
    out[t] = (v >= 0.f) ? v : expm1f(v);
}

// ---------------- launch ----------------
extern "C" void kernel_launch(void* const* d_in, const int* in_sizes, int n_in,
                              void* d_out, int out_size)
{
    const float* vert = (const float*)d_in[0];   // [4096,1433]
    const int*   edge = (const int*)  d_in[1];   // [4096,4096]
    const float* W    = (const float*)d_in[2];   // [1433,64]
    const float* a_l  = (const float*)d_in[3];   // [8,8]
    const float* a_r  = (const float*)d_in[4];   // [8,8]
    float* out = (float*)d_out;                  // [4096,64]

    fused_gemm_pack<<<GEMM_BLOCKS + PACK_BLOCKS, 256>>>(vert, W, edge);
    prep_scores<<<(NN * NH * 4) / 256, 256>>>(a_l, a_r);
    attn_kernel<<<dim3(SPLITS, NN / TIA), 256>>>();
    combine_kernel<<<(NN * FOUT) / 256, 256>>>(out);
}